// round 5
// baseline (speedup 1.0000x reference)
#include <cuda_runtime.h>
#include <cuda_bf16.h>
#include <cstdint>

// Problem constants
#define Bn   64
#define Cn   256
#define HWn  1024
#define B2n  128      // 2*B
// TEMPERATURE = 0.5  -> logits = 2 * sim

// ---------------- scratch (static __device__, no allocation) ----------------
__device__ __align__(16) __nv_bfloat16 g_feats[(size_t)HWn * B2n * Cn]; // 64MB
__device__ double g_acc = 0.0;
__device__ int    g_cnt = 0;

// ---------------- helpers ----------------
__device__ __forceinline__ uint32_t smem_u32(const void* p) {
    uint32_t a;
    asm("{ .reg .u64 t; cvta.to.shared.u64 t, %1; cvt.u32.u64 %0, t; }" : "=r"(a) : "l"(p));
    return a;
}
__device__ __forceinline__ void ldmatrix_x4(uint32_t* r, uint32_t addr) {
    asm volatile("ldmatrix.sync.aligned.m8n8.x4.shared.b16 {%0,%1,%2,%3}, [%4];"
                 : "=r"(r[0]), "=r"(r[1]), "=r"(r[2]), "=r"(r[3]) : "r"(addr));
}
__device__ __forceinline__ void ldmatrix_x2(uint32_t* r, uint32_t addr) {
    asm volatile("ldmatrix.sync.aligned.m8n8.x2.shared.b16 {%0,%1}, [%2];"
                 : "=r"(r[0]), "=r"(r[1]) : "r"(addr));
}
__device__ __forceinline__ void mma_bf16(float* d, const uint32_t* a, const uint32_t* b) {
    asm volatile(
        "mma.sync.aligned.m16n8k16.row.col.f32.bf16.bf16.f32 "
        "{%0,%1,%2,%3}, {%4,%5,%6,%7}, {%8,%9}, {%0,%1,%2,%3};"
        : "+f"(d[0]), "+f"(d[1]), "+f"(d[2]), "+f"(d[3])
        : "r"(a[0]), "r"(a[1]), "r"(a[2]), "r"(a[3]), "r"(b[0]), "r"(b[1]));
}

// ================= Pass 1: normalize + transpose to g_feats =================
__global__ void __launch_bounds__(256)
norm_transpose_kernel(const float* __restrict__ x, const float* __restrict__ y) {
    __shared__ float sm[32][Cn + 1];
    const int tid  = threadIdx.x;
    const int lane = tid & 31;
    const int wrp  = tid >> 5;
    const int b2   = blockIdx.y;
    const int hw0  = blockIdx.x * 32;

    const float* src = (b2 < Bn) ? x : y;
    const int b = b2 & (Bn - 1);
    const float* base = src + ((size_t)b * Cn) * HWn + hw0;

    #pragma unroll
    for (int k = 0; k < Cn / 8; k++) {
        int c = wrp + k * 8;
        sm[lane][c] = base[(size_t)c * HWn + lane];
    }
    __syncthreads();

    const float eps = 1.1920929e-07f;
    #pragma unroll
    for (int p = 0; p < 4; p++) {
        int hw = p * 8 + wrp;
        float v[8];
        float ss = 0.f;
        #pragma unroll
        for (int k = 0; k < 8; k++) {
            v[k] = sm[hw][lane + 32 * k];
            ss += v[k] * v[k];
        }
        #pragma unroll
        for (int o = 16; o > 0; o >>= 1) ss += __shfl_xor_sync(0xffffffffu, ss, o);
        float scale = 1.0f / fmaxf(sqrtf(ss), eps);
        __nv_bfloat16* out = g_feats + ((size_t)(hw0 + hw) * B2n + b2) * Cn;
        #pragma unroll
        for (int k = 0; k < 8; k++)
            out[lane + 32 * k] = __float2bfloat16(v[k] * scale);
    }
}

// ================= Pass 2: symmetric 128x128x256 Gram + log-softmax ========
// grid 1024, block 320 (10 warps). Warp = one 32x32 block of the upper
// triangle of the 4x4 grid of 32-blocks. Off-diag blocks feed row AND col sums.
#define PITCH_B   528                       // 264 bf16/row (256 data + 8 pad)
#define TILE_SZ   (128 * PITCH_B)           // 67584 B
#define NTHR2     320

__global__ void __launch_bounds__(NTHR2, 2)
pixel_kernel(float* __restrict__ d_out) {
    extern __shared__ __align__(16) char smem[];
    __shared__ float rs[128][4];   // per-row partial sums, one slot per 32-block
    __shared__ float pv[128];      // partner logits
    __shared__ float red[4];

    const int tid  = threadIdx.x;
    const int lane = tid & 31;
    const int w    = tid >> 5;     // 0..9

    // upper-triangle block map
    const int bi_t[10] = {0,0,0,0,1,1,1,2,2,3};
    const int bj_t[10] = {0,1,2,3,1,2,3,2,3,3};
    const int bi = bi_t[w], bj = bj_t[w];
    const int R = bi * 32, C = bj * 32;
    const bool diag = (bi == bj);

    // ---- stage tile: 128 rows x 512 B, pitch 528 B (4096 16B chunks) ----
    {
        const uint4* src = reinterpret_cast<const uint4*>(
            g_feats + (size_t)blockIdx.x * B2n * Cn);
        for (int idx = tid; idx < 4096; idx += NTHR2) {
            int r  = idx >> 5;
            int ch = idx & 31;
            *reinterpret_cast<uint4*>(smem + r * PITCH_B + ch * 16) = src[idx];
        }
    }
    __syncthreads();

    const uint32_t base  = smem_u32(smem);
    const uint32_t a_off = (uint32_t)(lane & 15) * PITCH_B + ((lane >> 4) & 1) * 16;
    const uint32_t b_off = (uint32_t)(lane & 7)  * PITCH_B + ((lane >> 3) & 1) * 16;

    float acc[2][4][4];
    #pragma unroll
    for (int mt = 0; mt < 2; mt++)
        #pragma unroll
        for (int nt = 0; nt < 4; nt++)
            #pragma unroll
            for (int e = 0; e < 4; e++) acc[mt][nt][e] = 0.f;

    #pragma unroll
    for (int ks = 0; ks < 16; ks++) {
        const uint32_t kb = (uint32_t)ks * 32;
        uint32_t a[2][4];
        #pragma unroll
        for (int mt = 0; mt < 2; mt++)
            ldmatrix_x4(a[mt], base + (uint32_t)(R + mt * 16) * PITCH_B + a_off + kb);
        #pragma unroll
        for (int nt = 0; nt < 4; nt++) {
            uint32_t b[2];
            ldmatrix_x2(b, base + (uint32_t)(C + nt * 8) * PITCH_B + b_off + kb);
            #pragma unroll
            for (int mt = 0; mt < 2; mt++)
                mma_bf16(acc[mt][nt], a[mt], b);
        }
    }

    // ---- epilogue: logits = 2*sim; skip diagonal; partner = row^64 ----
    const int qrow = lane >> 2;
    const int qcol = (lane & 3) * 2;
    float psum[2][2];                         // row sums [mt][h]
    float csum[4][2];                         // col sums [nt][parity]
    #pragma unroll
    for (int mt = 0; mt < 2; mt++) { psum[mt][0] = 0.f; psum[mt][1] = 0.f; }
    #pragma unroll
    for (int nt = 0; nt < 4; nt++) { csum[nt][0] = 0.f; csum[nt][1] = 0.f; }

    #pragma unroll
    for (int mt = 0; mt < 2; mt++)
        #pragma unroll
        for (int nt = 0; nt < 4; nt++)
            #pragma unroll
            for (int e = 0; e < 4; e++) {
                int row = R + mt * 16 + qrow + ((e >> 1) * 8);
                int col = C + nt * 8 + qcol + (e & 1);
                float v = 2.0f * acc[mt][nt][e];
                if (col != row) {
                    float ev = __expf(v);
                    psum[mt][e >> 1] += ev;
                    if (!diag) csum[nt][e & 1] += ev;
                }
                if (col == (row ^ 64)) { pv[row] = v; pv[col] = v; }
            }

    // row sums: reduce over quad (lane&3), lanes with lane&3==0 write slot bj
    #pragma unroll
    for (int mt = 0; mt < 2; mt++)
        #pragma unroll
        for (int h = 0; h < 2; h++) {
            float s = psum[mt][h];
            s += __shfl_xor_sync(0xffffffffu, s, 1);
            s += __shfl_xor_sync(0xffffffffu, s, 2);
            if ((lane & 3) == 0)
                rs[R + mt * 16 + qrow + 8 * h][bj] = s;
        }

    // col sums (off-diag only): reduce over qrow (lane>>2), lanes 0-3 write slot bi
    if (!diag) {
        #pragma unroll
        for (int nt = 0; nt < 4; nt++)
            #pragma unroll
            for (int p = 0; p < 2; p++) {
                float s = csum[nt][p];
                s += __shfl_xor_sync(0xffffffffu, s, 4);
                s += __shfl_xor_sync(0xffffffffu, s, 8);
                s += __shfl_xor_sync(0xffffffffu, s, 16);
                if (lane < 4)
                    rs[C + nt * 8 + (lane & 3) * 2 + p][bi] = s;
            }
    }
    __syncthreads();

    // ---- per-row loss, block reduce, global accumulate ----
    if (tid < 128) {
        float s = rs[tid][0] + rs[tid][1] + rs[tid][2] + rs[tid][3];
        float loss = pv[tid] - __logf(s);
        #pragma unroll
        for (int o = 16; o > 0; o >>= 1) loss += __shfl_xor_sync(0xffffffffu, loss, o);
        if (lane == 0) red[tid >> 5] = loss;
    }
    __syncthreads();
    if (tid == 0) {
        atomicAdd(&g_acc, (double)(red[0] + red[1] + red[2] + red[3]));
        __threadfence();
        if (atomicAdd(&g_cnt, 1) == HWn - 1) {     // last CTA finishes
            __threadfence();
            double total = atomicAdd(&g_acc, 0.0); // atomic read (L2-coherent)
            d_out[0] = (float)(-total / (double)((size_t)HWn * B2n));
            g_acc = 0.0;                            // reset for next graph replay
            __threadfence();
            g_cnt = 0;
        }
    }
}

// ================= launch =================
extern "C" void kernel_launch(void* const* d_in, const int* in_sizes, int n_in,
                              void* d_out, int out_size) {
    (void)in_sizes; (void)n_in; (void)out_size;
    cudaFuncSetAttribute(pixel_kernel, cudaFuncAttributeMaxDynamicSharedMemorySize, TILE_SZ);

    dim3 g1(HWn / 32, B2n);
    norm_transpose_kernel<<<g1, 256>>>((const float*)d_in[0], (const float*)d_in[1]);
    pixel_kernel<<<HWn, NTHR2, TILE_SZ>>>((float*)d_out);
}

// round 6
// speedup vs baseline: 1.3857x; 1.3857x over previous
#include <cuda_runtime.h>
#include <cuda_bf16.h>
#include <cstdint>

// Problem constants
#define Bn   64
#define Cn   256
#define HWn  1024
#define B2n  128      // 2*B
// TEMPERATURE = 0.5  -> logits = 2 * sim

// ---------------- scratch (static __device__, no allocation) ----------------
__device__ __align__(16) __nv_bfloat16 g_feats[(size_t)HWn * B2n * Cn]; // 64MB
__device__ double g_acc = 0.0;
__device__ int    g_cnt = 0;

// ---------------- helpers ----------------
__device__ __forceinline__ uint32_t smem_u32(const void* p) {
    uint32_t a;
    asm("{ .reg .u64 t; cvta.to.shared.u64 t, %1; cvt.u32.u64 %0, t; }" : "=r"(a) : "l"(p));
    return a;
}
__device__ __forceinline__ void ldmatrix_x4(uint32_t* r, uint32_t addr) {
    asm volatile("ldmatrix.sync.aligned.m8n8.x4.shared.b16 {%0,%1,%2,%3}, [%4];"
                 : "=r"(r[0]), "=r"(r[1]), "=r"(r[2]), "=r"(r[3]) : "r"(addr));
}
__device__ __forceinline__ void ldmatrix_x2(uint32_t* r, uint32_t addr) {
    asm volatile("ldmatrix.sync.aligned.m8n8.x2.shared.b16 {%0,%1}, [%2];"
                 : "=r"(r[0]), "=r"(r[1]) : "r"(addr));
}
__device__ __forceinline__ void mma_bf16(float* d, const uint32_t* a, const uint32_t* b) {
    asm volatile(
        "mma.sync.aligned.m16n8k16.row.col.f32.bf16.bf16.f32 "
        "{%0,%1,%2,%3}, {%4,%5,%6,%7}, {%8,%9}, {%0,%1,%2,%3};"
        : "+f"(d[0]), "+f"(d[1]), "+f"(d[2]), "+f"(d[3])
        : "r"(a[0]), "r"(a[1]), "r"(a[2]), "r"(a[3]), "r"(b[0]), "r"(b[1]));
}
__device__ __forceinline__ void cp_async16(uint32_t saddr, const void* gptr) {
    asm volatile("cp.async.cg.shared.global [%0], [%1], 16;"
                 :: "r"(saddr), "l"(gptr) : "memory");
}
#define CP_COMMIT() asm volatile("cp.async.commit_group;" ::: "memory")
#define CP_WAIT(n)  asm volatile("cp.async.wait_group %0;" :: "n"(n) : "memory")

// ================= Pass 1: normalize + transpose to g_feats =================
__global__ void __launch_bounds__(256)
norm_transpose_kernel(const float* __restrict__ x, const float* __restrict__ y) {
    __shared__ float sm[32][Cn + 1];
    const int tid  = threadIdx.x;
    const int lane = tid & 31;
    const int wrp  = tid >> 5;
    const int b2   = blockIdx.y;
    const int hw0  = blockIdx.x * 32;

    const float* src = (b2 < Bn) ? x : y;
    const int b = b2 & (Bn - 1);
    const float* base = src + ((size_t)b * Cn) * HWn + hw0;

    #pragma unroll
    for (int k = 0; k < Cn / 8; k++) {
        int c = wrp + k * 8;
        sm[lane][c] = base[(size_t)c * HWn + lane];
    }
    __syncthreads();

    const float eps = 1.1920929e-07f;
    #pragma unroll
    for (int p = 0; p < 4; p++) {
        int hw = p * 8 + wrp;
        float v[8];
        float ss = 0.f;
        #pragma unroll
        for (int k = 0; k < 8; k++) {
            v[k] = sm[hw][lane + 32 * k];
            ss += v[k] * v[k];
        }
        #pragma unroll
        for (int o = 16; o > 0; o >>= 1) ss += __shfl_xor_sync(0xffffffffu, ss, o);
        float scale = 1.0f / fmaxf(sqrtf(ss), eps);
        __nv_bfloat16* out = g_feats + ((size_t)(hw0 + hw) * B2n + b2) * Cn;
        #pragma unroll
        for (int k = 0; k < 8; k++)
            out[lane + 32 * k] = __float2bfloat16(v[k] * scale);
    }
}

// ================= Pass 2: symmetric Gram, K-pipelined cp.async staging =====
// grid 1024, block 320 (10 warps = 10 upper-tri 32x32 blocks).
// SMEM: two K-halves, each 128 rows x 128 bf16 (256B data + 16B pad = 272B pitch).
#define PITCH_H   272
#define HALF_SZ   (128 * PITCH_H)          // 34816 B
#define SMEM_DYN  (2 * HALF_SZ)            // 69632 B
#define NTHR2     320

__global__ void __launch_bounds__(NTHR2, 3)
pixel_kernel(float* __restrict__ d_out) {
    extern __shared__ __align__(16) char smem[];
    __shared__ float rs[128][4];
    __shared__ float pv[128];
    __shared__ float red[4];

    const int tid  = threadIdx.x;
    const int lane = tid & 31;
    const int w    = tid >> 5;                       // 0..9
    const int bi   = (0xE9500u >> (w << 1)) & 3;     // {0,0,0,0,1,1,1,2,2,3}
    const int bj   = (0xFB9E4u >> (w << 1)) & 3;     // {0,1,2,3,1,2,3,2,3,3}
    const int R = bi * 32, C = bj * 32;
    const bool diag = (bi == bj);

    // ---- issue cp.async for both K-halves (each: 128 rows x 16 chunks) ----
    const uint32_t sbase = smem_u32(smem);
    {
        const char* gsrc = reinterpret_cast<const char*>(
            g_feats + (size_t)blockIdx.x * B2n * Cn);
        #pragma unroll
        for (int h = 0; h < 2; h++) {
            const char* gh = gsrc + h * 256;         // half column offset (128 bf16)
            const uint32_t sb = sbase + h * HALF_SZ;
            #pragma unroll
            for (int j = 0; j < 6; j++) {
                int idx = tid + j * NTHR2;           // 0..1919
                int r = idx >> 4, ch = idx & 15;
                cp_async16(sb + r * PITCH_H + ch * 16, gh + r * 512 + ch * 16);
            }
            if (tid < 128) {                          // remaining 128 chunks
                int idx = 1920 + tid;
                int r = idx >> 4, ch = idx & 15;
                cp_async16(sb + r * PITCH_H + ch * 16, gh + r * 512 + ch * 16);
            }
            CP_COMMIT();
        }
    }

    const uint32_t a_off = (uint32_t)(lane & 15) * PITCH_H + ((lane >> 4) & 1) * 16;
    const uint32_t b_off = (uint32_t)(lane & 7)  * PITCH_H + ((lane >> 3) & 1) * 16;

    float acc[2][4][4];
    #pragma unroll
    for (int mt = 0; mt < 2; mt++)
        #pragma unroll
        for (int nt = 0; nt < 4; nt++)
            #pragma unroll
            for (int e = 0; e < 4; e++) acc[mt][nt][e] = 0.f;

    // ---- K-pipelined MMA: half 0 while half 1 is in flight ----
    #pragma unroll
    for (int h = 0; h < 2; h++) {
        if (h == 0) CP_WAIT(1); else CP_WAIT(0);
        __syncthreads();
        const uint32_t hb = sbase + h * HALF_SZ;
        #pragma unroll
        for (int ks = 0; ks < 8; ks++) {
            const uint32_t kb = (uint32_t)ks * 32;
            uint32_t a[2][4];
            #pragma unroll
            for (int mt = 0; mt < 2; mt++)
                ldmatrix_x4(a[mt], hb + (uint32_t)(R + mt * 16) * PITCH_H + a_off + kb);
            #pragma unroll
            for (int nt = 0; nt < 4; nt++) {
                uint32_t b[2];
                ldmatrix_x2(b, hb + (uint32_t)(C + nt * 8) * PITCH_H + b_off + kb);
                #pragma unroll
                for (int mt = 0; mt < 2; mt++)
                    mma_bf16(acc[mt][nt], a[mt], b);
            }
        }
    }

    // ---- epilogue: logits = 2*sim; skip diagonal; partner = row^64 ----
    const int qrow = lane >> 2;
    const int qcol = (lane & 3) * 2;
    float psum[2][2];
    float csum[4][2];
    #pragma unroll
    for (int mt = 0; mt < 2; mt++) { psum[mt][0] = 0.f; psum[mt][1] = 0.f; }
    #pragma unroll
    for (int nt = 0; nt < 4; nt++) { csum[nt][0] = 0.f; csum[nt][1] = 0.f; }

    #pragma unroll
    for (int mt = 0; mt < 2; mt++)
        #pragma unroll
        for (int nt = 0; nt < 4; nt++)
            #pragma unroll
            for (int e = 0; e < 4; e++) {
                int row = R + mt * 16 + qrow + ((e >> 1) * 8);
                int col = C + nt * 8 + qcol + (e & 1);
                float v = 2.0f * acc[mt][nt][e];
                if (col != row) {
                    float ev = __expf(v);
                    psum[mt][e >> 1] += ev;
                    if (!diag) csum[nt][e & 1] += ev;
                }
                if (col == (row ^ 64)) { pv[row] = v; pv[col] = v; }
            }

    // row sums -> rs[.][bj]
    #pragma unroll
    for (int mt = 0; mt < 2; mt++)
        #pragma unroll
        for (int hh = 0; hh < 2; hh++) {
            float s = psum[mt][hh];
            s += __shfl_xor_sync(0xffffffffu, s, 1);
            s += __shfl_xor_sync(0xffffffffu, s, 2);
            if ((lane & 3) == 0)
                rs[R + mt * 16 + qrow + 8 * hh][bj] = s;
        }
    // col sums (off-diag) -> rs[.][bi]
    if (!diag) {
        #pragma unroll
        for (int nt = 0; nt < 4; nt++)
            #pragma unroll
            for (int p = 0; p < 2; p++) {
                float s = csum[nt][p];
                s += __shfl_xor_sync(0xffffffffu, s, 4);
                s += __shfl_xor_sync(0xffffffffu, s, 8);
                s += __shfl_xor_sync(0xffffffffu, s, 16);
                if (lane < 4)
                    rs[C + nt * 8 + (lane & 3) * 2 + p][bi] = s;
            }
    }
    __syncthreads();

    // ---- per-row loss, block reduce, global accumulate, last-CTA finish ----
    if (tid < 128) {
        float s = rs[tid][0] + rs[tid][1] + rs[tid][2] + rs[tid][3];
        float loss = pv[tid] - __logf(s);
        #pragma unroll
        for (int o = 16; o > 0; o >>= 1) loss += __shfl_xor_sync(0xffffffffu, loss, o);
        if (lane == 0) red[tid >> 5] = loss;
    }
    __syncthreads();
    if (tid == 0) {
        atomicAdd(&g_acc, (double)(red[0] + red[1] + red[2] + red[3]));
        __threadfence();
        if (atomicAdd(&g_cnt, 1) == HWn - 1) {
            __threadfence();
            double total = atomicAdd(&g_acc, 0.0);
            d_out[0] = (float)(-total / (double)((size_t)HWn * B2n));
            g_acc = 0.0;
            __threadfence();
            g_cnt = 0;
        }
    }
}

// ================= launch =================
extern "C" void kernel_launch(void* const* d_in, const int* in_sizes, int n_in,
                              void* d_out, int out_size) {
    (void)in_sizes; (void)n_in; (void)out_size;
    cudaFuncSetAttribute(pixel_kernel, cudaFuncAttributeMaxDynamicSharedMemorySize, SMEM_DYN);

    dim3 g1(HWn / 32, B2n);
    norm_transpose_kernel<<<g1, 256>>>((const float*)d_in[0], (const float*)d_in[1]);
    pixel_kernel<<<HWn, NTHR2, SMEM_DYN>>>((float*)d_out);
}